// round 2
// baseline (speedup 1.0000x reference)
#include <cuda_runtime.h>
#include <math.h>

// Problem constants: feat [65536, 256], n_per_graph = 512 -> B = 128 batches, d = 256.
#define NB   128
#define NPG  512
#define DIM  256
#define DD   (DIM*DIM)          // 65536
#define BD   (NB*DD)            // 8388608

#define NOISE_RATE 0.01f

// Scratch (allocation-free rule: device globals)
__device__ float g_A[BD];
__device__ float g_Y0[BD];
__device__ float g_Y1[BD];
__device__ float g_Z0[BD];
__device__ float g_Z1[BD];
__device__ float g_T[BD];
__device__ float g_mean[NB*DIM];
__device__ float g_v[NB*DIM];
__device__ float g_norm[NB];

// ---------------------------------------------------------------------------
// mean over nodes per graph: one block per batch, one thread per column
// ---------------------------------------------------------------------------
__global__ void mean_kernel(const float* __restrict__ feat,
                            const float* __restrict__ noise) {
    int b = blockIdx.x, c = threadIdx.x;
    const float* F  = feat  + (size_t)b * NPG * DIM + c;
    const float* Nz = noise + (size_t)b * NPG * DIM + c;
    float s = 0.f;
    #pragma unroll 8
    for (int n = 0; n < NPG; ++n)
        s += F[(size_t)n * DIM] + NOISE_RATE * Nz[(size_t)n * DIM];
    g_mean[b * DIM + c] = s * (1.f / NPG);
}

// ---------------------------------------------------------------------------
// covariance: cov[b] = diff^T diff / (NPG-1), diff computed on the fly.
// 128x128 output tile per block, K-tile 8, 256 threads, 8x8 per thread.
// ---------------------------------------------------------------------------
__global__ void __launch_bounds__(256) cov_kernel(const float* __restrict__ feat,
                                                  const float* __restrict__ noise) {
    int b  = blockIdx.z;
    int i0 = blockIdx.y * 128, j0 = blockIdx.x * 128;
    __shared__ float Ds[8][128];
    __shared__ float Es[8][128];
    int tid = threadIdx.x;
    int lk = tid >> 5, lq = (tid & 31) * 4;     // loader: k-row, col quad
    int tx = tid & 15, ty = tid >> 4;           // compute: 16x16 thread grid

    float acc[8][8];
    #pragma unroll
    for (int i = 0; i < 8; i++)
        #pragma unroll
        for (int j = 0; j < 8; j++) acc[i][j] = 0.f;

    float4 mi = *(const float4*)&g_mean[b * DIM + i0 + lq];
    float4 mj = *(const float4*)&g_mean[b * DIM + j0 + lq];
    const float* F  = feat  + (size_t)b * NPG * DIM;
    const float* Nz = noise + (size_t)b * NPG * DIM;

    for (int kt = 0; kt < NPG; kt += 8) {
        size_t row = (size_t)(kt + lk) * DIM;
        float4 f1 = *(const float4*)&F [row + i0 + lq];
        float4 n1 = *(const float4*)&Nz[row + i0 + lq];
        float4 f2 = *(const float4*)&F [row + j0 + lq];
        float4 n2 = *(const float4*)&Nz[row + j0 + lq];
        float4 di, dj;
        di.x = f1.x + NOISE_RATE * n1.x - mi.x;
        di.y = f1.y + NOISE_RATE * n1.y - mi.y;
        di.z = f1.z + NOISE_RATE * n1.z - mi.z;
        di.w = f1.w + NOISE_RATE * n1.w - mi.w;
        dj.x = f2.x + NOISE_RATE * n2.x - mj.x;
        dj.y = f2.y + NOISE_RATE * n2.y - mj.y;
        dj.z = f2.z + NOISE_RATE * n2.z - mj.z;
        dj.w = f2.w + NOISE_RATE * n2.w - mj.w;
        __syncthreads();
        *(float4*)&Ds[lk][lq] = di;
        *(float4*)&Es[lk][lq] = dj;
        __syncthreads();
        #pragma unroll
        for (int k = 0; k < 8; ++k) {
            float a[8], bb[8];
            *(float4*)(a)     = *(const float4*)&Ds[k][ty * 8];
            *(float4*)(a + 4) = *(const float4*)&Ds[k][ty * 8 + 4];
            *(float4*)(bb)     = *(const float4*)&Es[k][tx * 8];
            *(float4*)(bb + 4) = *(const float4*)&Es[k][tx * 8 + 4];
            #pragma unroll
            for (int i = 0; i < 8; i++)
                #pragma unroll
                for (int j = 0; j < 8; j++)
                    acc[i][j] += a[i] * bb[j];
        }
    }
    const float sc = 1.f / (NPG - 1);
    float* Cv = g_A + (size_t)b * DD;
    #pragma unroll
    for (int i = 0; i < 8; i++) {
        int r = i0 + ty * 8 + i;
        #pragma unroll
        for (int j = 0; j < 8; j += 4) {
            float4 v;
            v.x = acc[i][j + 0] * sc;
            v.y = acc[i][j + 1] * sc;
            v.z = acc[i][j + 2] * sc;
            v.w = acc[i][j + 3] * sc;
            *(float4*)&Cv[(size_t)r * DIM + j0 + tx * 8 + j] = v;
        }
    }
}

// ---------------------------------------------------------------------------
// trace of cov -> g_norm  (one block per batch)
// ---------------------------------------------------------------------------
__global__ void trace_kernel() {
    int b = blockIdx.x, tid = threadIdx.x;
    float v = g_A[(size_t)b * DD + (size_t)tid * (DIM + 1)];
    #pragma unroll
    for (int o = 16; o; o >>= 1) v += __shfl_xor_sync(0xffffffffu, v, o);
    __shared__ float sm[8];
    if ((tid & 31) == 0) sm[tid >> 5] = v;
    __syncthreads();
    if (tid == 0) {
        float s = 0.f;
        #pragma unroll
        for (int w = 0; w < 8; w++) s += sm[w];
        g_norm[b] = s;
    }
}

// ---------------------------------------------------------------------------
// A = cov / trace;  Z0 = 1.5*I - 0.5*A
// ---------------------------------------------------------------------------
__global__ void init_kernel() {
    int b = blockIdx.y;
    int e = blockIdx.x * blockDim.x + threadIdx.x;   // 0..DD-1
    size_t idx = (size_t)b * DD + e;
    float a = g_A[idx] * (1.f / g_norm[b]);
    g_A[idx] = a;
    int r = e >> 8, c = e & 255;
    g_Z0[idx] = (r == c ? 1.5f : 0.f) - 0.5f * a;
}

// ---------------------------------------------------------------------------
// batched 256x256x256 fp32 GEMM.  MODE 0: C = A@B.  MODE 1: C = 1.5I - 0.5*(A@B)
// 128x128 tile / block, 256 threads, 8x8 per thread, K-tile 8.
// As padded to 132 cols: conflict-free transposed stores.
// ---------------------------------------------------------------------------
template <int MODE>
__global__ void __launch_bounds__(256) gemm256(const float* __restrict__ Ag,
                                               const float* __restrict__ Bg,
                                               float* __restrict__ Cg) {
    int b = blockIdx.z;
    const float* A  = Ag + (size_t)b * DD;
    const float* Bm = Bg + (size_t)b * DD;
    float* C = Cg + (size_t)b * DD;
    int m0 = blockIdx.y * 128, n0 = blockIdx.x * 128;

    __shared__ float As[8][132];
    __shared__ float Bs[8][128];
    int tid = threadIdx.x;
    int tx = tid & 15, ty = tid >> 4;
    int alm = tid >> 1, akq = (tid & 1) * 4;     // A loader: row, k quad
    int blk = tid >> 5, bnq = (tid & 31) * 4;    // B loader: k-row, col quad

    float acc[8][8];
    #pragma unroll
    for (int i = 0; i < 8; i++)
        #pragma unroll
        for (int j = 0; j < 8; j++) acc[i][j] = 0.f;

    for (int kt = 0; kt < DIM; kt += 8) {
        float4 av = *(const float4*)&A [(size_t)(m0 + alm) * DIM + kt + akq];
        float4 bv = *(const float4*)&Bm[(size_t)(kt + blk) * DIM + n0 + bnq];
        __syncthreads();
        As[akq + 0][alm] = av.x;
        As[akq + 1][alm] = av.y;
        As[akq + 2][alm] = av.z;
        As[akq + 3][alm] = av.w;
        *(float4*)&Bs[blk][bnq] = bv;
        __syncthreads();
        #pragma unroll
        for (int k = 0; k < 8; ++k) {
            float a[8], bb[8];
            *(float4*)(a)     = *(const float4*)&As[k][ty * 8];
            *(float4*)(a + 4) = *(const float4*)&As[k][ty * 8 + 4];
            *(float4*)(bb)     = *(const float4*)&Bs[k][tx * 8];
            *(float4*)(bb + 4) = *(const float4*)&Bs[k][tx * 8 + 4];
            #pragma unroll
            for (int i = 0; i < 8; i++)
                #pragma unroll
                for (int j = 0; j < 8; j++)
                    acc[i][j] += a[i] * bb[j];
        }
    }
    #pragma unroll
    for (int i = 0; i < 8; i++) {
        int r = m0 + ty * 8 + i;
        #pragma unroll
        for (int j = 0; j < 8; j += 4) {
            int c = n0 + tx * 8 + j;
            float4 v;
            if (MODE == 0) {
                v.x = acc[i][j + 0];
                v.y = acc[i][j + 1];
                v.z = acc[i][j + 2];
                v.w = acc[i][j + 3];
            } else {
                v.x = (r == c + 0 ? 1.5f : 0.f) - 0.5f * acc[i][j + 0];
                v.y = (r == c + 1 ? 1.5f : 0.f) - 0.5f * acc[i][j + 1];
                v.z = (r == c + 2 ? 1.5f : 0.f) - 0.5f * acc[i][j + 2];
                v.w = (r == c + 3 ? 1.5f : 0.f) - 0.5f * acc[i][j + 3];
            }
            *(float4*)&C[(size_t)r * DIM + c] = v;
        }
    }
}

// ---------------------------------------------------------------------------
// out[b] = scale * (M[b] @ vin[b]).  scale = sqrt(norm[b]) if useScale.
// One block per batch, 8 warps, warp per row (strided), shfl reduce.
// ---------------------------------------------------------------------------
__global__ void matvec_kernel(const float* __restrict__ M,
                              const float* __restrict__ vin,
                              float* __restrict__ outp, int useScale) {
    int b = blockIdx.x;
    __shared__ float vs[DIM];
    int tid = threadIdx.x;
    vs[tid] = vin[b * DIM + tid];
    __syncthreads();
    int warp = tid >> 5, lane = tid & 31;
    const float* Mb = M + (size_t)b * DD;
    float scale = useScale ? sqrtf(g_norm[b]) : 1.f;
    for (int r = warp; r < DIM; r += 8) {
        float s = 0.f;
        #pragma unroll
        for (int c = lane; c < DIM; c += 32) s += Mb[(size_t)r * DIM + c] * vs[c];
        #pragma unroll
        for (int o = 16; o; o >>= 1) s += __shfl_xor_sync(0xffffffffu, s, o);
        if (lane == 0) outp[b * DIM + r] = s * scale;
    }
}

// ---------------------------------------------------------------------------
extern "C" void kernel_launch(void* const* d_in, const int* in_sizes, int n_in,
                              void* d_out, int out_size) {
    const float* feat  = (const float*)d_in[0];
    const float* noise = (const float*)d_in[1];
    float* out = (float*)d_out;

    float *A, *Y0, *Y1, *Z0, *Z1, *T, *Mean, *Vv;
    cudaGetSymbolAddress((void**)&A,    g_A);
    cudaGetSymbolAddress((void**)&Y0,   g_Y0);
    cudaGetSymbolAddress((void**)&Y1,   g_Y1);
    cudaGetSymbolAddress((void**)&Z0,   g_Z0);
    cudaGetSymbolAddress((void**)&Z1,   g_Z1);
    cudaGetSymbolAddress((void**)&T,    g_T);
    cudaGetSymbolAddress((void**)&Mean, g_mean);
    cudaGetSymbolAddress((void**)&Vv,   g_v);

    mean_kernel<<<NB, DIM>>>(feat, noise);
    cov_kernel<<<dim3(2, 2, NB), 256>>>(feat, noise);
    trace_kernel<<<NB, DIM>>>();
    init_kernel<<<dim3(DD / 256, NB), 256>>>();

    dim3 gg(2, 2, NB);
    // Y = A @ Z0  (Z0 = 1.5I - 0.5A)
    gemm256<0><<<gg, 256>>>(A, Z0, Y0);

    float* Yc[2] = {Y0, Y1};
    float* Zc[2] = {Z0, Z1};
    int cur = 0;
    for (int it = 0; it < 3; ++it) {          // ITERN=5 -> 3 middle iterations
        gemm256<1><<<gg, 256>>>(Zc[cur], Yc[cur], T);      // T = 1.5I - 0.5*Z@Y
        gemm256<0><<<gg, 256>>>(Yc[cur], T, Yc[1 - cur]);  // Y' = Y@T
        gemm256<0><<<gg, 256>>>(T, Zc[cur], Zc[1 - cur]);  // Z' = T@Z
        cur ^= 1;
    }
    // S = 1.5I - 0.5*(Z@Y); out = sqrt(norm) * Y @ (S @ mean)
    gemm256<1><<<gg, 256>>>(Zc[cur], Yc[cur], T);
    matvec_kernel<<<NB, DIM>>>(T, Mean, Vv, 0);
    matvec_kernel<<<NB, DIM>>>(Yc[cur], Vv, out, 1);
}